// round 2
// baseline (speedup 1.0000x reference)
#include <cuda_runtime.h>

// Problem constants (fixed by the reference)
#define BDIM   32
#define CDIM   256
#define HW     4096          // 64*64
#define KTAPS  3
#define BN_EPS 1e-5f

// Scratch (allocation-free rule: __device__ globals)
__device__ float g_gap [BDIM * CDIM];          // [B, C] plane means
__device__ float g_filt[BDIM * KTAPS * CDIM];  // [B, 3, C] sigmoid filters

// ---------------------------------------------------------------------------
// Kernel A: global average pool — one block per (b, c) plane of 4096 floats.
// 128 threads * 8 float4 = 4096 elements, warp-shuffle reduce.
// ---------------------------------------------------------------------------
__global__ void gap_kernel(const float* __restrict__ x) {
    const int plane = blockIdx.x;                       // 0 .. B*C-1
    const float4* __restrict__ p =
        reinterpret_cast<const float4*>(x + (size_t)plane * HW);
    const int t = threadIdx.x;                          // 128 threads
    float s = 0.0f;
#pragma unroll
    for (int i = 0; i < 8; ++i) {
        float4 v = p[t + i * 128];
        s += (v.x + v.y) + (v.z + v.w);
    }
#pragma unroll
    for (int o = 16; o; o >>= 1)
        s += __shfl_xor_sync(0xffffffffu, s, o);
    __shared__ float ws[4];
    if ((t & 31) == 0) ws[t >> 5] = s;
    __syncthreads();
    if (t == 0)
        g_gap[plane] = (ws[0] + ws[1] + ws[2] + ws[3]) * (1.0f / (float)HW);
}

// ---------------------------------------------------------------------------
// Kernel B: filt[b, o] = sigmoid(BN(gap[b,:] . conv_w[o,:]))  (o = k*C + c)
// One block per batch sample, 256 threads, 3 outputs per thread.
// conv_w stays hot in L2 across the 32 blocks (786 KB).
// ---------------------------------------------------------------------------
__global__ void filt_kernel(const float* __restrict__ conv_w,
                            const float* __restrict__ bn_w,
                            const float* __restrict__ bn_b,
                            const float* __restrict__ bn_mean,
                            const float* __restrict__ bn_var) {
    const int b = blockIdx.x;
    const int t = threadIdx.x;                          // 256 threads
    __shared__ float sg[CDIM];
    sg[t] = g_gap[b * CDIM + t];
    __syncthreads();
#pragma unroll
    for (int j = 0; j < KTAPS; ++j) {
        const int o = t + j * CDIM;
        const float* __restrict__ w = conv_w + (size_t)o * CDIM;
        float acc = 0.0f;
#pragma unroll 8
        for (int c = 0; c < CDIM; ++c) acc = fmaf(sg[c], w[c], acc);
        float f = (acc - bn_mean[o]) * rsqrtf(bn_var[o] + BN_EPS) * bn_w[o] + bn_b[o];
        g_filt[b * KTAPS * CDIM + o] = 1.0f / (1.0f + __expf(-f));
    }
}

// ---------------------------------------------------------------------------
// Kernel C: main fused pass.
//   out[b,c,hw] = (f0*x[b,pc] + f1*x[b,c] + f2*x[b,nc]) * gamma[c] + x[b,c]*beta[c]
// with reflect indices pc/nc. Rolling registers: each x element loaded ONCE.
// grid = (HW/(128*4), CDIM/CSEG, B) = (8, 4, 32) = 1024 blocks, 128 threads.
// ---------------------------------------------------------------------------
#define CSEG     64
#define CTHREADS 128

__global__ __launch_bounds__(CTHREADS)
void main_kernel(const float* __restrict__ x,
                 const float* __restrict__ gamma,
                 const float* __restrict__ beta,
                 float* __restrict__ out) {
    const int t   = threadIdx.x;
    const int b   = blockIdx.z;
    const int c0  = blockIdx.y * CSEG;
    const int hw4 = blockIdx.x * CTHREADS + t;          // float4 index in plane

    __shared__ float sf0[CSEG], sf1[CSEG], sf2[CSEG], sgm[CSEG], sbt[CSEG];
    if (t < CSEG) {
        const int c = c0 + t;
        const float* __restrict__ fb = g_filt + b * KTAPS * CDIM;
        sf0[t] = fb[c];
        sf1[t] = fb[CDIM + c];
        sf2[t] = fb[2 * CDIM + c];
        sgm[t] = gamma[c];
        sbt[t] = beta[c];
    }
    __syncthreads();

    const int STRIDE = HW / 4;                          // float4 per channel
    const float4* __restrict__ xb =
        reinterpret_cast<const float4*>(x) + (size_t)b * CDIM * STRIDE + hw4;
    float4* __restrict__ ob =
        reinterpret_cast<float4*>(out) + (size_t)b * CDIM * STRIDE + hw4;

    // Seed rolling registers. Reflect pad: prev of c=0 is x[1].
    const int cm = (c0 == 0) ? 1 : (c0 - 1);
    float4 xm = xb[(size_t)cm * STRIDE];
    float4 xc = xb[(size_t)c0 * STRIDE];

#pragma unroll 4
    for (int c = c0; c < c0 + CSEG; ++c) {
        const int cn = (c == CDIM - 1) ? (CDIM - 2) : (c + 1);
        float4 xn = xb[(size_t)cn * STRIDE];
        const int ci = c - c0;
        const float f0 = sf0[ci], f1 = sf1[ci], f2 = sf2[ci];
        const float gm = sgm[ci], bt = sbt[ci];
        float4 r;
        r.x = fmaf(fmaf(f0, xm.x, fmaf(f1, xc.x, f2 * xn.x)), gm, xc.x * bt);
        r.y = fmaf(fmaf(f0, xm.y, fmaf(f1, xc.y, f2 * xn.y)), gm, xc.y * bt);
        r.z = fmaf(fmaf(f0, xm.z, fmaf(f1, xc.z, f2 * xn.z)), gm, xc.z * bt);
        r.w = fmaf(fmaf(f0, xm.w, fmaf(f1, xc.w, f2 * xn.w)), gm, xc.w * bt);
        ob[(size_t)c * STRIDE] = r;
        xm = xc;
        xc = xn;
    }
}

// ---------------------------------------------------------------------------
// Launch: three graph-capturable kernels, default stream.
// Input order (metadata): x, conv_w, bn_w, bn_b, bn_mean, bn_var, gamma, beta
// ---------------------------------------------------------------------------
extern "C" void kernel_launch(void* const* d_in, const int* in_sizes, int n_in,
                              void* d_out, int out_size) {
    const float* x       = (const float*)d_in[0];
    const float* conv_w  = (const float*)d_in[1];
    const float* bn_w    = (const float*)d_in[2];
    const float* bn_b    = (const float*)d_in[3];
    const float* bn_mean = (const float*)d_in[4];
    const float* bn_var  = (const float*)d_in[5];
    const float* gamma   = (const float*)d_in[6];
    const float* beta    = (const float*)d_in[7];
    float* out = (float*)d_out;

    gap_kernel<<<BDIM * CDIM, 128>>>(x);
    filt_kernel<<<BDIM, CDIM>>>(conv_w, bn_w, bn_b, bn_mean, bn_var);
    dim3 grid(HW / (CTHREADS * 4), CDIM / CSEG, BDIM);
    main_kernel<<<grid, CTHREADS>>>(x, gamma, beta, out);
}

// round 3
// speedup vs baseline: 2.1275x; 2.1275x over previous
#include <cuda_runtime.h>

// Problem constants (fixed by the reference)
#define BDIM   32
#define CDIM   256
#define HW     4096          // 64*64
#define KTAPS  3
#define KC     (KTAPS * CDIM)   // 768
#define BN_EPS 1e-5f

// Scratch (allocation-free rule: __device__ globals)
__device__ float g_gap [BDIM * CDIM];          // [B, C] plane means
__device__ float g_filt[BDIM * KC];            // [B, 3, C] sigmoid filters

// ---------------------------------------------------------------------------
// Kernel A: global average pool — one block per (b, c) plane of 4096 floats.
// ---------------------------------------------------------------------------
__global__ void gap_kernel(const float* __restrict__ x) {
    const int plane = blockIdx.x;                       // 0 .. B*C-1
    const float4* __restrict__ p =
        reinterpret_cast<const float4*>(x + (size_t)plane * HW);
    const int t = threadIdx.x;                          // 128 threads
    float s = 0.0f;
#pragma unroll
    for (int i = 0; i < 8; ++i) {
        float4 v = p[t + i * 128];
        s += (v.x + v.y) + (v.z + v.w);
    }
#pragma unroll
    for (int o = 16; o; o >>= 1)
        s += __shfl_xor_sync(0xffffffffu, s, o);
    __shared__ float ws[4];
    if ((t & 31) == 0) ws[t >> 5] = s;
    __syncthreads();
    if (t == 0)
        g_gap[plane] = (ws[0] + ws[1] + ws[2] + ws[3]) * (1.0f / (float)HW);
}

// ---------------------------------------------------------------------------
// Kernel B (REWRITTEN): warp-per-output GEMV.
// grid = (KC/128, B), block = 256 threads (8 warps). Each warp computes 16
// outputs; for each output all 32 lanes read CONSECUTIVE float4s of one
// conv_w row (coalesced), dot against gap (shared), butterfly-reduce.
// ---------------------------------------------------------------------------
__global__ __launch_bounds__(256)
void filt_kernel(const float* __restrict__ conv_w,
                 const float* __restrict__ bn_w,
                 const float* __restrict__ bn_b,
                 const float* __restrict__ bn_mean,
                 const float* __restrict__ bn_var) {
    const int b    = blockIdx.y;
    const int warp = threadIdx.x >> 5;      // 0..7
    const int lid  = threadIdx.x & 31;

    __shared__ __align__(16) float sg[CDIM];
    for (int i = threadIdx.x; i < CDIM; i += 256)
        sg[i] = g_gap[b * CDIM + i];
    __syncthreads();

    // Per-lane gap slices (uniform across the warp's 16 outputs)
    const float4 g1 = *reinterpret_cast<const float4*>(&sg[4 * lid]);
    const float4 g2 = *reinterpret_cast<const float4*>(&sg[128 + 4 * lid]);

#pragma unroll
    for (int i = 0; i < 16; ++i) {
        const int o = blockIdx.x * 128 + warp * 16 + i;  // output row
        const float4* __restrict__ w4 =
            reinterpret_cast<const float4*>(conv_w + (size_t)o * CDIM);
        const float4 wa = w4[lid];        // c = 4*lid .. 4*lid+3
        const float4 wb = w4[lid + 32];   // c = 128+4*lid ..
        float acc = wa.x * g1.x;
        acc = fmaf(wa.y, g1.y, acc);
        acc = fmaf(wa.z, g1.z, acc);
        acc = fmaf(wa.w, g1.w, acc);
        acc = fmaf(wb.x, g2.x, acc);
        acc = fmaf(wb.y, g2.y, acc);
        acc = fmaf(wb.z, g2.z, acc);
        acc = fmaf(wb.w, g2.w, acc);
#pragma unroll
        for (int off = 16; off; off >>= 1)
            acc += __shfl_xor_sync(0xffffffffu, acc, off);
        if (lid == 0) {
            float f = (acc - bn_mean[o]) * rsqrtf(bn_var[o] + BN_EPS) * bn_w[o]
                      + bn_b[o];
            g_filt[b * KC + o] = 1.0f / (1.0f + __expf(-f));
        }
    }
}

// ---------------------------------------------------------------------------
// Kernel C: main fused pass (unchanged — rolling-register channel walk,
// one LDG.128 + one STG.128 per element).
// ---------------------------------------------------------------------------
#define CSEG     64
#define CTHREADS 128

__global__ __launch_bounds__(CTHREADS)
void main_kernel(const float* __restrict__ x,
                 const float* __restrict__ gamma,
                 const float* __restrict__ beta,
                 float* __restrict__ out) {
    const int t   = threadIdx.x;
    const int b   = blockIdx.z;
    const int c0  = blockIdx.y * CSEG;
    const int hw4 = blockIdx.x * CTHREADS + t;          // float4 index in plane

    __shared__ float sf0[CSEG], sf1[CSEG], sf2[CSEG], sgm[CSEG], sbt[CSEG];
    if (t < CSEG) {
        const int c = c0 + t;
        const float* __restrict__ fb = g_filt + b * KC;
        sf0[t] = fb[c];
        sf1[t] = fb[CDIM + c];
        sf2[t] = fb[2 * CDIM + c];
        sgm[t] = gamma[c];
        sbt[t] = beta[c];
    }
    __syncthreads();

    const int STRIDE = HW / 4;                          // float4 per channel
    const float4* __restrict__ xb =
        reinterpret_cast<const float4*>(x) + (size_t)b * CDIM * STRIDE + hw4;
    float4* __restrict__ ob =
        reinterpret_cast<float4*>(out) + (size_t)b * CDIM * STRIDE + hw4;

    // Seed rolling registers. Reflect pad: prev of c=0 is x[1].
    const int cm = (c0 == 0) ? 1 : (c0 - 1);
    float4 xm = xb[(size_t)cm * STRIDE];
    float4 xc = xb[(size_t)c0 * STRIDE];

#pragma unroll 4
    for (int c = c0; c < c0 + CSEG; ++c) {
        const int cn = (c == CDIM - 1) ? (CDIM - 2) : (c + 1);
        float4 xn = xb[(size_t)cn * STRIDE];
        const int ci = c - c0;
        const float f0 = sf0[ci], f1 = sf1[ci], f2 = sf2[ci];
        const float gm = sgm[ci], bt = sbt[ci];
        float4 r;
        r.x = fmaf(fmaf(f0, xm.x, fmaf(f1, xc.x, f2 * xn.x)), gm, xc.x * bt);
        r.y = fmaf(fmaf(f0, xm.y, fmaf(f1, xc.y, f2 * xn.y)), gm, xc.y * bt);
        r.z = fmaf(fmaf(f0, xm.z, fmaf(f1, xc.z, f2 * xn.z)), gm, xc.z * bt);
        r.w = fmaf(fmaf(f0, xm.w, fmaf(f1, xc.w, f2 * xn.w)), gm, xc.w * bt);
        ob[(size_t)c * STRIDE] = r;
        xm = xc;
        xc = xn;
    }
}

// ---------------------------------------------------------------------------
// Launch (graph-capturable, default stream).
// Input order: x, conv_w, bn_w, bn_b, bn_mean, bn_var, gamma, beta
// ---------------------------------------------------------------------------
extern "C" void kernel_launch(void* const* d_in, const int* in_sizes, int n_in,
                              void* d_out, int out_size) {
    const float* x       = (const float*)d_in[0];
    const float* conv_w  = (const float*)d_in[1];
    const float* bn_w    = (const float*)d_in[2];
    const float* bn_b    = (const float*)d_in[3];
    const float* bn_mean = (const float*)d_in[4];
    const float* bn_var  = (const float*)d_in[5];
    const float* gamma   = (const float*)d_in[6];
    const float* beta    = (const float*)d_in[7];
    float* out = (float*)d_out;

    gap_kernel<<<BDIM * CDIM, 128>>>(x);
    dim3 fgrid(KC / 128, BDIM);
    filt_kernel<<<fgrid, 256>>>(conv_w, bn_w, bn_b, bn_mean, bn_var);
    dim3 grid(HW / (CTHREADS * 4), CDIM / CSEG, BDIM);
    main_kernel<<<grid, CTHREADS>>>(x, gamma, beta, out);
}

// round 4
// speedup vs baseline: 2.1283x; 1.0004x over previous
#include <cuda_runtime.h>

// Problem constants (fixed by the reference)
#define BDIM   32
#define CDIM   256
#define HW     4096          // 64*64
#define KTAPS  3
#define KC     (KTAPS * CDIM)   // 768
#define BN_EPS 1e-5f

// Scratch (allocation-free rule: __device__ globals)
__device__ float g_gap [BDIM * CDIM];          // [B, C] plane means
__device__ float g_filt[BDIM * KC];            // [B, 3, C] sigmoid filters

// ---------------------------------------------------------------------------
// Kernel A: global average pool — one block per (b, c) plane of 4096 floats.
// Normal (caching) loads on purpose: this pass warms L2 with x for kernel C.
// ---------------------------------------------------------------------------
__global__ void gap_kernel(const float* __restrict__ x) {
    const int plane = blockIdx.x;                       // 0 .. B*C-1
    const float4* __restrict__ p =
        reinterpret_cast<const float4*>(x + (size_t)plane * HW);
    const int t = threadIdx.x;                          // 128 threads
    float s = 0.0f;
#pragma unroll
    for (int i = 0; i < 8; ++i) {
        float4 v = p[t + i * 128];
        s += (v.x + v.y) + (v.z + v.w);
    }
#pragma unroll
    for (int o = 16; o; o >>= 1)
        s += __shfl_xor_sync(0xffffffffu, s, o);
    __shared__ float ws[4];
    if ((t & 31) == 0) ws[t >> 5] = s;
    __syncthreads();
    if (t == 0)
        g_gap[plane] = (ws[0] + ws[1] + ws[2] + ws[3]) * (1.0f / (float)HW);
}

// ---------------------------------------------------------------------------
// Kernel B: warp-per-output GEMV (coalesced conv_w rows), unchanged.
// ---------------------------------------------------------------------------
__global__ __launch_bounds__(256)
void filt_kernel(const float* __restrict__ conv_w,
                 const float* __restrict__ bn_w,
                 const float* __restrict__ bn_b,
                 const float* __restrict__ bn_mean,
                 const float* __restrict__ bn_var) {
    const int b    = blockIdx.y;
    const int warp = threadIdx.x >> 5;      // 0..7
    const int lid  = threadIdx.x & 31;

    __shared__ __align__(16) float sg[CDIM];
    for (int i = threadIdx.x; i < CDIM; i += 256)
        sg[i] = g_gap[b * CDIM + i];
    __syncthreads();

    const float4 g1 = *reinterpret_cast<const float4*>(&sg[4 * lid]);
    const float4 g2 = *reinterpret_cast<const float4*>(&sg[128 + 4 * lid]);

#pragma unroll
    for (int i = 0; i < 16; ++i) {
        const int o = blockIdx.x * 128 + warp * 16 + i;  // output row
        const float4* __restrict__ w4 =
            reinterpret_cast<const float4*>(conv_w + (size_t)o * CDIM);
        const float4 wa = w4[lid];        // c = 4*lid .. 4*lid+3
        const float4 wb = w4[lid + 32];   // c = 128+4*lid ..
        float acc = wa.x * g1.x;
        acc = fmaf(wa.y, g1.y, acc);
        acc = fmaf(wa.z, g1.z, acc);
        acc = fmaf(wa.w, g1.w, acc);
        acc = fmaf(wb.x, g2.x, acc);
        acc = fmaf(wb.y, g2.y, acc);
        acc = fmaf(wb.z, g2.z, acc);
        acc = fmaf(wb.w, g2.w, acc);
#pragma unroll
        for (int off = 16; off; off >>= 1)
            acc += __shfl_xor_sync(0xffffffffu, acc, off);
        if (lid == 0) {
            float f = (acc - bn_mean[o]) * rsqrtf(bn_var[o] + BN_EPS) * bn_w[o]
                      + bn_b[o];
            g_filt[b * KC + o] = 1.0f / (1.0f + __expf(-f));
        }
    }
}

// ---------------------------------------------------------------------------
// Kernel C: main fused pass. Rolling-register channel walk (1 LDG + 1 STG
// per element). NEW: stores are __stcs (evict-first) so the never-re-read
// output stream doesn't evict the L2-resident x left behind by gap_kernel.
// ---------------------------------------------------------------------------
#define CSEG     64
#define CTHREADS 128

__global__ __launch_bounds__(CTHREADS)
void main_kernel(const float* __restrict__ x,
                 const float* __restrict__ gamma,
                 const float* __restrict__ beta,
                 float* __restrict__ out) {
    const int t   = threadIdx.x;
    const int b   = blockIdx.z;
    const int c0  = blockIdx.y * CSEG;
    const int hw4 = blockIdx.x * CTHREADS + t;          // float4 index in plane

    __shared__ float sf0[CSEG], sf1[CSEG], sf2[CSEG], sgm[CSEG], sbt[CSEG];
    if (t < CSEG) {
        const int c = c0 + t;
        const float* __restrict__ fb = g_filt + b * KC;
        sf0[t] = fb[c];
        sf1[t] = fb[CDIM + c];
        sf2[t] = fb[2 * CDIM + c];
        sgm[t] = gamma[c];
        sbt[t] = beta[c];
    }
    __syncthreads();

    const int STRIDE = HW / 4;                          // float4 per channel
    const float4* __restrict__ xb =
        reinterpret_cast<const float4*>(x) + (size_t)b * CDIM * STRIDE + hw4;
    float4* __restrict__ ob =
        reinterpret_cast<float4*>(out) + (size_t)b * CDIM * STRIDE + hw4;

    // Seed rolling registers. Reflect pad: prev of c=0 is x[1].
    const int cm = (c0 == 0) ? 1 : (c0 - 1);
    float4 xm = xb[(size_t)cm * STRIDE];
    float4 xc = xb[(size_t)c0 * STRIDE];

#pragma unroll 4
    for (int c = c0; c < c0 + CSEG; ++c) {
        const int cn = (c == CDIM - 1) ? (CDIM - 2) : (c + 1);
        float4 xn = xb[(size_t)cn * STRIDE];
        const int ci = c - c0;
        const float f0 = sf0[ci], f1 = sf1[ci], f2 = sf2[ci];
        const float gm = sgm[ci], bt = sbt[ci];
        float4 r;
        r.x = fmaf(fmaf(f0, xm.x, fmaf(f1, xc.x, f2 * xn.x)), gm, xc.x * bt);
        r.y = fmaf(fmaf(f0, xm.y, fmaf(f1, xc.y, f2 * xn.y)), gm, xc.y * bt);
        r.z = fmaf(fmaf(f0, xm.z, fmaf(f1, xc.z, f2 * xn.z)), gm, xc.z * bt);
        r.w = fmaf(fmaf(f0, xm.w, fmaf(f1, xc.w, f2 * xn.w)), gm, xc.w * bt);
        __stcs(&ob[(size_t)c * STRIDE], r);             // evict-first store
        xm = xc;
        xc = xn;
    }
}

// ---------------------------------------------------------------------------
// Launch (graph-capturable, default stream).
// Input order: x, conv_w, bn_w, bn_b, bn_mean, bn_var, gamma, beta
// ---------------------------------------------------------------------------
extern "C" void kernel_launch(void* const* d_in, const int* in_sizes, int n_in,
                              void* d_out, int out_size) {
    const float* x       = (const float*)d_in[0];
    const float* conv_w  = (const float*)d_in[1];
    const float* bn_w    = (const float*)d_in[2];
    const float* bn_b    = (const float*)d_in[3];
    const float* bn_mean = (const float*)d_in[4];
    const float* bn_var  = (const float*)d_in[5];
    const float* gamma   = (const float*)d_in[6];
    const float* beta    = (const float*)d_in[7];
    float* out = (float*)d_out;

    gap_kernel<<<BDIM * CDIM, 128>>>(x);
    dim3 fgrid(KC / 128, BDIM);
    filt_kernel<<<fgrid, 256>>>(conv_w, bn_w, bn_b, bn_mean, bn_var);
    dim3 grid(HW / (CTHREADS * 4), CDIM / CSEG, BDIM);
    main_kernel<<<grid, CTHREADS>>>(x, gamma, beta, out);
}

// round 5
// speedup vs baseline: 2.1855x; 1.0269x over previous
#include <cuda_runtime.h>

// Problem constants (fixed by the reference)
#define BDIM   32
#define CDIM   256
#define HW     4096          // 64*64
#define KTAPS  3
#define KC     (KTAPS * CDIM)   // 768
#define BN_EPS 1e-5f

// Scratch (allocation-free rule: __device__ globals)
__device__ float g_gap [BDIM * CDIM];          // [B, C] plane means
__device__ float g_filt[BDIM * KC];            // [B, 3, C] sigmoid filters

// ---------------------------------------------------------------------------
// Kernel A: global average pool — one block per (b, c) plane of 4096 floats.
// ---------------------------------------------------------------------------
__global__ void gap_kernel(const float* __restrict__ x) {
    const int plane = blockIdx.x;                       // 0 .. B*C-1
    const float4* __restrict__ p =
        reinterpret_cast<const float4*>(x + (size_t)plane * HW);
    const int t = threadIdx.x;                          // 128 threads
    float s = 0.0f;
#pragma unroll
    for (int i = 0; i < 8; ++i) {
        float4 v = p[t + i * 128];
        s += (v.x + v.y) + (v.z + v.w);
    }
#pragma unroll
    for (int o = 16; o; o >>= 1)
        s += __shfl_xor_sync(0xffffffffu, s, o);
    __shared__ float ws[4];
    if ((t & 31) == 0) ws[t >> 5] = s;
    __syncthreads();
    if (t == 0)
        g_gap[plane] = (ws[0] + ws[1] + ws[2] + ws[3]) * (1.0f / (float)HW);
}

// ---------------------------------------------------------------------------
// Kernel B: warp-per-output GEMV. Launched with PDL; syncs on gap_kernel
// before reading g_gap.
// ---------------------------------------------------------------------------
__global__ __launch_bounds__(256)
void filt_kernel(const float* __restrict__ conv_w,
                 const float* __restrict__ bn_w,
                 const float* __restrict__ bn_b,
                 const float* __restrict__ bn_mean,
                 const float* __restrict__ bn_var) {
    const int b    = blockIdx.y;
    const int warp = threadIdx.x >> 5;      // 0..7
    const int lid  = threadIdx.x & 31;

#if __CUDA_ARCH__ >= 900
    cudaGridDependencySynchronize();        // wait for gap_kernel's g_gap
#endif

    __shared__ __align__(16) float sg[CDIM];
    for (int i = threadIdx.x; i < CDIM; i += 256)
        sg[i] = g_gap[b * CDIM + i];
    __syncthreads();

    const float4 g1 = *reinterpret_cast<const float4*>(&sg[4 * lid]);
    const float4 g2 = *reinterpret_cast<const float4*>(&sg[128 + 4 * lid]);

#pragma unroll
    for (int i = 0; i < 16; ++i) {
        const int o = blockIdx.x * 128 + warp * 16 + i;  // output row
        const float4* __restrict__ w4 =
            reinterpret_cast<const float4*>(conv_w + (size_t)o * CDIM);
        const float4 wa = w4[lid];        // c = 4*lid .. 4*lid+3
        const float4 wb = w4[lid + 32];   // c = 128+4*lid ..
        float acc = wa.x * g1.x;
        acc = fmaf(wa.y, g1.y, acc);
        acc = fmaf(wa.z, g1.z, acc);
        acc = fmaf(wa.w, g1.w, acc);
        acc = fmaf(wb.x, g2.x, acc);
        acc = fmaf(wb.y, g2.y, acc);
        acc = fmaf(wb.z, g2.z, acc);
        acc = fmaf(wb.w, g2.w, acc);
#pragma unroll
        for (int off = 16; off; off >>= 1)
            acc += __shfl_xor_sync(0xffffffffu, acc, off);
        if (lid == 0) {
            float f = (acc - bn_mean[o]) * rsqrtf(bn_var[o] + BN_EPS) * bn_w[o]
                      + bn_b[o];
            g_filt[b * KC + o] = 1.0f / (1.0f + __expf(-f));
        }
    }
}

// ---------------------------------------------------------------------------
// Kernel C: main fused pass. Rolling-register channel walk, unroll 8 for
// deeper MLP. PDL: the two seed x-loads issue BEFORE the grid-dependency
// sync (they don't depend on filt), hiding filt_kernel entirely.
// ---------------------------------------------------------------------------
#define CSEG     64
#define CTHREADS 128

__global__ __launch_bounds__(CTHREADS)
void main_kernel(const float* __restrict__ x,
                 const float* __restrict__ gamma,
                 const float* __restrict__ beta,
                 float* __restrict__ out) {
    const int t   = threadIdx.x;
    const int b   = blockIdx.z;
    const int c0  = blockIdx.y * CSEG;
    const int hw4 = blockIdx.x * CTHREADS + t;          // float4 index in plane

    const int STRIDE = HW / 4;                          // float4 per channel
    const float4* __restrict__ xb =
        reinterpret_cast<const float4*>(x) + (size_t)b * CDIM * STRIDE + hw4;
    float4* __restrict__ ob =
        reinterpret_cast<float4*>(out) + (size_t)b * CDIM * STRIDE + hw4;

    // Seed rolling registers early (independent of filt_kernel's output).
    const int cm = (c0 == 0) ? 1 : (c0 - 1);
    float4 xm = xb[(size_t)cm * STRIDE];
    float4 xc = xb[(size_t)c0 * STRIDE];

#if __CUDA_ARCH__ >= 900
    cudaGridDependencySynchronize();        // wait for filt_kernel's g_filt
#endif

    __shared__ float sf0[CSEG], sf1[CSEG], sf2[CSEG], sgm[CSEG], sbt[CSEG];
    if (t < CSEG) {
        const int c = c0 + t;
        const float* __restrict__ fb = g_filt + b * KC;
        sf0[t] = fb[c];
        sf1[t] = fb[CDIM + c];
        sf2[t] = fb[2 * CDIM + c];
        sgm[t] = gamma[c];
        sbt[t] = beta[c];
    }
    __syncthreads();

#pragma unroll 8
    for (int c = c0; c < c0 + CSEG; ++c) {
        const int cn = (c == CDIM - 1) ? (CDIM - 2) : (c + 1);
        float4 xn = xb[(size_t)cn * STRIDE];
        const int ci = c - c0;
        const float f0 = sf0[ci], f1 = sf1[ci], f2 = sf2[ci];
        const float gm = sgm[ci], bt = sbt[ci];
        float4 r;
        r.x = fmaf(fmaf(f0, xm.x, fmaf(f1, xc.x, f2 * xn.x)), gm, xc.x * bt);
        r.y = fmaf(fmaf(f0, xm.y, fmaf(f1, xc.y, f2 * xn.y)), gm, xc.y * bt);
        r.z = fmaf(fmaf(f0, xm.z, fmaf(f1, xc.z, f2 * xn.z)), gm, xc.z * bt);
        r.w = fmaf(fmaf(f0, xm.w, fmaf(f1, xc.w, f2 * xn.w)), gm, xc.w * bt);
        __stcs(&ob[(size_t)c * STRIDE], r);             // evict-first store
        xm = xc;
        xc = xn;
    }
}

// ---------------------------------------------------------------------------
// Launch (graph-capturable). filt and main use programmatic stream
// serialization (PDL) so each consumer's prologue overlaps its producer.
// Input order: x, conv_w, bn_w, bn_b, bn_mean, bn_var, gamma, beta
// ---------------------------------------------------------------------------
extern "C" void kernel_launch(void* const* d_in, const int* in_sizes, int n_in,
                              void* d_out, int out_size) {
    const float* x       = (const float*)d_in[0];
    const float* conv_w  = (const float*)d_in[1];
    const float* bn_w    = (const float*)d_in[2];
    const float* bn_b    = (const float*)d_in[3];
    const float* bn_mean = (const float*)d_in[4];
    const float* bn_var  = (const float*)d_in[5];
    const float* gamma   = (const float*)d_in[6];
    const float* beta    = (const float*)d_in[7];
    float* out = (float*)d_out;

    gap_kernel<<<BDIM * CDIM, 128>>>(x);

    cudaLaunchAttribute pdl[1];
    pdl[0].id = cudaLaunchAttributeProgrammaticStreamSerialization;
    pdl[0].val.programmaticStreamSerializationAllowed = 1;

    {   // filt_kernel with PDL
        cudaLaunchConfig_t cfg = {};
        cfg.gridDim  = dim3(KC / 128, BDIM, 1);
        cfg.blockDim = dim3(256, 1, 1);
        cfg.stream   = 0;
        cfg.attrs    = pdl;
        cfg.numAttrs = 1;
        cudaLaunchKernelEx(&cfg, filt_kernel,
                           conv_w, bn_w, bn_b, bn_mean, bn_var);
    }
    {   // main_kernel with PDL
        cudaLaunchConfig_t cfg = {};
        cfg.gridDim  = dim3(HW / (CTHREADS * 4), CDIM / CSEG, BDIM);
        cfg.blockDim = dim3(CTHREADS, 1, 1);
        cfg.stream   = 0;
        cfg.attrs    = pdl;
        cfg.numAttrs = 1;
        cudaLaunchKernelEx(&cfg, main_kernel, x, gamma, beta, out);
    }
}

// round 6
// speedup vs baseline: 2.1965x; 1.0051x over previous
#include <cuda_runtime.h>

// Problem constants (fixed by the reference)
#define BDIM   32
#define CDIM   256
#define HW     4096          // 64*64
#define KTAPS  3
#define KC     (KTAPS * CDIM)   // 768
#define BN_EPS 1e-5f

// Scratch (allocation-free rule: __device__ globals)
__device__ float g_gap [BDIM * CDIM];          // [B, C] plane means
__device__ float g_filt[BDIM * KC];            // [B, 3, C] sigmoid filters

// ---------------------------------------------------------------------------
// Kernel A: global average pool — one block per (b, c) plane of 4096 floats.
// ---------------------------------------------------------------------------
__global__ void gap_kernel(const float* __restrict__ x) {
    const int plane = blockIdx.x;                       // 0 .. B*C-1
    const float4* __restrict__ p =
        reinterpret_cast<const float4*>(x + (size_t)plane * HW);
    const int t = threadIdx.x;                          // 128 threads
    float s = 0.0f;
#pragma unroll
    for (int i = 0; i < 8; ++i) {
        float4 v = p[t + i * 128];
        s += (v.x + v.y) + (v.z + v.w);
    }
#pragma unroll
    for (int o = 16; o; o >>= 1)
        s += __shfl_xor_sync(0xffffffffu, s, o);
    __shared__ float ws[4];
    if ((t & 31) == 0) ws[t >> 5] = s;
    __syncthreads();
    if (t == 0)
        g_gap[plane] = (ws[0] + ws[1] + ws[2] + ws[3]) * (1.0f / (float)HW);
}

// ---------------------------------------------------------------------------
// Kernel B: warp-per-output GEMV (unchanged). PDL-synced on gap_kernel.
// ---------------------------------------------------------------------------
__global__ __launch_bounds__(256)
void filt_kernel(const float* __restrict__ conv_w,
                 const float* __restrict__ bn_w,
                 const float* __restrict__ bn_b,
                 const float* __restrict__ bn_mean,
                 const float* __restrict__ bn_var) {
    const int b    = blockIdx.y;
    const int warp = threadIdx.x >> 5;      // 0..7
    const int lid  = threadIdx.x & 31;

#if __CUDA_ARCH__ >= 900
    cudaGridDependencySynchronize();        // wait for gap_kernel's g_gap
#endif

    __shared__ __align__(16) float sg[CDIM];
    for (int i = threadIdx.x; i < CDIM; i += 256)
        sg[i] = g_gap[b * CDIM + i];
    __syncthreads();

    const float4 g1 = *reinterpret_cast<const float4*>(&sg[4 * lid]);
    const float4 g2 = *reinterpret_cast<const float4*>(&sg[128 + 4 * lid]);

#pragma unroll
    for (int i = 0; i < 16; ++i) {
        const int o = blockIdx.x * 128 + warp * 16 + i;  // output row
        const float4* __restrict__ w4 =
            reinterpret_cast<const float4*>(conv_w + (size_t)o * CDIM);
        const float4 wa = w4[lid];        // c = 4*lid .. 4*lid+3
        const float4 wb = w4[lid + 32];   // c = 128+4*lid ..
        float acc = wa.x * g1.x;
        acc = fmaf(wa.y, g1.y, acc);
        acc = fmaf(wa.z, g1.z, acc);
        acc = fmaf(wa.w, g1.w, acc);
        acc = fmaf(wb.x, g2.x, acc);
        acc = fmaf(wb.y, g2.y, acc);
        acc = fmaf(wb.z, g2.z, acc);
        acc = fmaf(wb.w, g2.w, acc);
#pragma unroll
        for (int off = 16; off; off >>= 1)
            acc += __shfl_xor_sync(0xffffffffu, acc, off);
        if (lid == 0) {
            float f = (acc - bn_mean[o]) * rsqrtf(bn_var[o] + BN_EPS) * bn_w[o]
                      + bn_b[o];
            g_filt[b * KC + o] = 1.0f / (1.0f + __expf(-f));
        }
    }
}

// ---------------------------------------------------------------------------
// Kernel C: main fused pass. CSEG halved 64 -> 32: grid 2048 blocks = 8192
// warps (~86% of chip warp slots, was 43%) for deeper chip-wide MLP.
// __ldcs reads (x dead after this kernel) + __stcs writes.
// ---------------------------------------------------------------------------
#define CSEG     32
#define CTHREADS 128

__global__ __launch_bounds__(CTHREADS)
void main_kernel(const float* __restrict__ x,
                 const float* __restrict__ gamma,
                 const float* __restrict__ beta,
                 float* __restrict__ out) {
    const int t   = threadIdx.x;
    const int b   = blockIdx.z;
    const int c0  = blockIdx.y * CSEG;
    const int hw4 = blockIdx.x * CTHREADS + t;          // float4 index in plane

    const int STRIDE = HW / 4;                          // float4 per channel
    const float4* __restrict__ xb =
        reinterpret_cast<const float4*>(x) + (size_t)b * CDIM * STRIDE + hw4;
    float4* __restrict__ ob =
        reinterpret_cast<float4*>(out) + (size_t)b * CDIM * STRIDE + hw4;

    // Seed rolling registers early (independent of filt_kernel's output).
    const int cm = (c0 == 0) ? 1 : (c0 - 1);
    float4 xm = __ldcs(&xb[(size_t)cm * STRIDE]);
    float4 xc = __ldcs(&xb[(size_t)c0 * STRIDE]);

#if __CUDA_ARCH__ >= 900
    cudaGridDependencySynchronize();        // wait for filt_kernel's g_filt
#endif

    __shared__ float sf0[CSEG], sf1[CSEG], sf2[CSEG], sgm[CSEG], sbt[CSEG];
    if (t < CSEG) {
        const int c = c0 + t;
        const float* __restrict__ fb = g_filt + b * KC;
        sf0[t] = fb[c];
        sf1[t] = fb[CDIM + c];
        sf2[t] = fb[2 * CDIM + c];
        sgm[t] = gamma[c];
        sbt[t] = beta[c];
    }
    __syncthreads();

#pragma unroll 8
    for (int c = c0; c < c0 + CSEG; ++c) {
        const int cn = (c == CDIM - 1) ? (CDIM - 2) : (c + 1);
        float4 xn = __ldcs(&xb[(size_t)cn * STRIDE]);
        const int ci = c - c0;
        const float f0 = sf0[ci], f1 = sf1[ci], f2 = sf2[ci];
        const float gm = sgm[ci], bt = sbt[ci];
        float4 r;
        r.x = fmaf(fmaf(f0, xm.x, fmaf(f1, xc.x, f2 * xn.x)), gm, xc.x * bt);
        r.y = fmaf(fmaf(f0, xm.y, fmaf(f1, xc.y, f2 * xn.y)), gm, xc.y * bt);
        r.z = fmaf(fmaf(f0, xm.z, fmaf(f1, xc.z, f2 * xn.z)), gm, xc.z * bt);
        r.w = fmaf(fmaf(f0, xm.w, fmaf(f1, xc.w, f2 * xn.w)), gm, xc.w * bt);
        __stcs(&ob[(size_t)c * STRIDE], r);             // evict-first store
        xm = xc;
        xc = xn;
    }
}

// ---------------------------------------------------------------------------
// Launch (graph-capturable). PDL chains gap -> filt -> main.
// Input order: x, conv_w, bn_w, bn_b, bn_mean, bn_var, gamma, beta
// ---------------------------------------------------------------------------
extern "C" void kernel_launch(void* const* d_in, const int* in_sizes, int n_in,
                              void* d_out, int out_size) {
    const float* x       = (const float*)d_in[0];
    const float* conv_w  = (const float*)d_in[1];
    const float* bn_w    = (const float*)d_in[2];
    const float* bn_b    = (const float*)d_in[3];
    const float* bn_mean = (const float*)d_in[4];
    const float* bn_var  = (const float*)d_in[5];
    const float* gamma   = (const float*)d_in[6];
    const float* beta    = (const float*)d_in[7];
    float* out = (float*)d_out;

    gap_kernel<<<BDIM * CDIM, 128>>>(x);

    cudaLaunchAttribute pdl[1];
    pdl[0].id = cudaLaunchAttributeProgrammaticStreamSerialization;
    pdl[0].val.programmaticStreamSerializationAllowed = 1;

    {   // filt_kernel with PDL
        cudaLaunchConfig_t cfg = {};
        cfg.gridDim  = dim3(KC / 128, BDIM, 1);
        cfg.blockDim = dim3(256, 1, 1);
        cfg.stream   = 0;
        cfg.attrs    = pdl;
        cfg.numAttrs = 1;
        cudaLaunchKernelEx(&cfg, filt_kernel,
                           conv_w, bn_w, bn_b, bn_mean, bn_var);
    }
    {   // main_kernel with PDL
        cudaLaunchConfig_t cfg = {};
        cfg.gridDim  = dim3(HW / (CTHREADS * 4), CDIM / CSEG, BDIM);
        cfg.blockDim = dim3(CTHREADS, 1, 1);
        cfg.stream   = 0;
        cfg.attrs    = pdl;
        cfg.numAttrs = 1;
        cudaLaunchKernelEx(&cfg, main_kernel, x, gamma, beta, out);
    }
}